// round 4
// baseline (speedup 1.0000x reference)
#include <cuda_runtime.h>
#include <cuda_bf16.h>
#include <cstdint>

#define N_TOK   4096
#define DM      2048
#define WIDTH   16384
#define TOPK    64
#define CAND    96
#define CAP     256

// ---------------- device-global scratch (no allocations allowed) --------------
__device__ __nv_bfloat16 g_Xh[(size_t)N_TOK * DM];
__device__ __nv_bfloat16 g_Wh[(size_t)WIDTH * DM];
__device__ float         g_WdecT[(size_t)WIDTH * DM];
__device__ float         g_dense[(size_t)N_TOK * WIDTH];
__device__ int           g_cidx[(size_t)N_TOK * CAP];
__device__ int           g_ccnt[N_TOK];
__device__ int           g_tidx[(size_t)N_TOK * TOPK];
__device__ float         g_tval[(size_t)N_TOK * TOPK];

// ---------------- helpers -----------------------------------------------------
__device__ __forceinline__ uint32_t smem_u32(const void* p) {
    uint32_t a;
    asm("{ .reg .u64 t; cvta.to.shared.u64 t, %1; cvt.u32.u64 %0, t; }" : "=r"(a) : "l"(p));
    return a;
}
__device__ __forceinline__ void cp16(uint32_t s, const void* g) {
    asm volatile("cp.async.cg.shared.global [%0], [%1], 16;" :: "r"(s), "l"(g) : "memory");
}
#define CP_COMMIT() asm volatile("cp.async.commit_group;" ::: "memory")
#define CP_WAIT(n)  asm volatile("cp.async.wait_group %0;" :: "n"(n) : "memory")

__device__ __forceinline__ void ldsm_x4(uint32_t* r, uint32_t addr) {
    asm volatile("ldmatrix.sync.aligned.m8n8.x4.shared.b16 {%0,%1,%2,%3}, [%4];"
                 : "=r"(r[0]), "=r"(r[1]), "=r"(r[2]), "=r"(r[3]) : "r"(addr));
}
__device__ __forceinline__ void ldsm_x2(uint32_t* r, uint32_t addr) {
    asm volatile("ldmatrix.sync.aligned.m8n8.x2.shared.b16 {%0,%1}, [%2];"
                 : "=r"(r[0]), "=r"(r[1]) : "r"(addr));
}
__device__ __forceinline__ void mma_bf16(float* c, const uint32_t* a, const uint32_t* b) {
    asm volatile("mma.sync.aligned.m16n8k16.row.col.f32.bf16.bf16.f32 "
                 "{%0,%1,%2,%3}, {%4,%5,%6,%7}, {%8,%9}, {%0,%1,%2,%3};"
                 : "+f"(c[0]), "+f"(c[1]), "+f"(c[2]), "+f"(c[3])
                 : "r"(a[0]), "r"(a[1]), "r"(a[2]), "r"(a[3]), "r"(b[0]), "r"(b[1]));
}

// ---------------- prep kernels ------------------------------------------------
__global__ void k_prep_x(const float* __restrict__ src) {
    const int n = N_TOK * DM;
    for (int i = blockIdx.x * blockDim.x + threadIdx.x; i < n; i += gridDim.x * blockDim.x)
        g_Xh[i] = __float2bfloat16(src[i]);
}
__global__ void k_prep_w(const float* __restrict__ src) {
    const size_t n = (size_t)WIDTH * DM;
    for (size_t i = blockIdx.x * (size_t)blockDim.x + threadIdx.x; i < n;
         i += (size_t)gridDim.x * blockDim.x)
        g_Wh[i] = __float2bfloat16(src[i]);
}
// W_dec[DM][WIDTH] -> g_WdecT[WIDTH][DM]
__global__ void k_transpose(const float* __restrict__ in) {
    __shared__ float t[32][33];
    int j0 = blockIdx.x * 32, d0 = blockIdx.y * 32;
    int tx = threadIdx.x, ty = threadIdx.y;   // block (32, 8)
#pragma unroll
    for (int k = 0; k < 32; k += 8)
        t[ty + k][tx] = in[(size_t)(d0 + ty + k) * WIDTH + j0 + tx];
    __syncthreads();
#pragma unroll
    for (int k = 0; k < 32; k += 8)
        g_WdecT[(size_t)(j0 + ty + k) * DM + d0 + tx] = t[tx][ty + k];
}

__global__ void k_zero_feat(float* __restrict__ feat) {
    const size_t n = (size_t)N_TOK * WIDTH / 4;
    float4 z = make_float4(0.f, 0.f, 0.f, 0.f);
    for (size_t i = blockIdx.x * (size_t)blockDim.x + threadIdx.x; i < n;
         i += (size_t)gridDim.x * blockDim.x)
        ((float4*)feat)[i] = z;
}

// ---------------- encoder: single-bf16 mma.sync GEMM + bias + relu -------------
// CTA tile 128x128, KC=64, 2-stage cp.async. Warp grid 2x4, warp tile 64x32.
#define TM 128
#define TN 128
#define KC 64
#define NCHUNK (DM / KC)     // 32
#define T_B 16384
#define STAGE_BYTES 32768
#define ENC_SMEM (2 * STAGE_BYTES)

#define SWZ_KB(kb, r) ((kb) ^ (((r) & 7) << 4))

__global__ void __launch_bounds__(256, 2)
k_encoder(const float* __restrict__ b_enc, float* __restrict__ dense)
{
    extern __shared__ char smem[];
    const uint32_t sb = smem_u32(smem);
    const int tid  = threadIdx.x;
    const int wid  = tid >> 5;
    const int lane = tid & 31;
    const int m0 = blockIdx.x * TM;
    const int j0 = blockIdx.y * TN;
    const int wm0 = (wid >> 2) * 64;
    const int wn0 = (wid & 3) * 32;

    auto load_stage = [&](int c, int s) {
        const int k0 = c * KC;
        const uint32_t st = sb + s * STAGE_BYTES;
#pragma unroll
        for (int i = 0; i < 4; i++) {
            int idx = tid + i * 256;           // 0..1023
            int r = idx >> 3, w = idx & 7;
            uint32_t soff = (uint32_t)(r * 128 + SWZ_KB(w * 16, r));
            cp16(st + soff, g_Xh + (size_t)(m0 + r) * DM + k0 + w * 8);
        }
#pragma unroll
        for (int i = 0; i < 4; i++) {
            int idx = tid + i * 256;
            int r = idx >> 3, w = idx & 7;
            uint32_t soff = (uint32_t)(r * 128 + SWZ_KB(w * 16, r));
            cp16(st + T_B + soff, g_Wh + (size_t)(j0 + r) * DM + k0 + w * 8);
        }
    };

    float acc[4][4][4];
#pragma unroll
    for (int mf = 0; mf < 4; mf++)
#pragma unroll
        for (int nf = 0; nf < 4; nf++)
#pragma unroll
            for (int q = 0; q < 4; q++) acc[mf][nf][q] = 0.0f;

    load_stage(0, 0);
    CP_COMMIT();

    const int aRowLane = lane & 15;
    const int aKgLane  = (lane >> 4);
    const int bRowLane = lane & 7;
    const int bKgLane  = (lane >> 3) & 1;

    for (int c = 0; c < NCHUNK; c++) {
        if (c + 1 < NCHUNK) {
            load_stage(c + 1, (c + 1) & 1);
            CP_COMMIT();
            CP_WAIT(1);
        } else {
            CP_WAIT(0);
        }
        __syncthreads();

        const uint32_t st = sb + (c & 1) * STAGE_BYTES;
#pragma unroll
        for (int ks = 0; ks < 4; ks++) {
            uint32_t ah[4][4], bh[4][2];
#pragma unroll
            for (int mf = 0; mf < 4; mf++) {
                int r = wm0 + mf * 16 + aRowLane;
                int kb = ks * 32 + aKgLane * 16;
                ldsm_x4(ah[mf], st + (uint32_t)(r * 128 + SWZ_KB(kb, r)));
            }
#pragma unroll
            for (int nf = 0; nf < 4; nf++) {
                int r = wn0 + nf * 8 + bRowLane;
                int kb = ks * 32 + bKgLane * 16;
                ldsm_x2(bh[nf], st + T_B + (uint32_t)(r * 128 + SWZ_KB(kb, r)));
            }
#pragma unroll
            for (int mf = 0; mf < 4; mf++)
#pragma unroll
                for (int nf = 0; nf < 4; nf++)
                    mma_bf16(acc[mf][nf], ah[mf], bh[nf]);
        }
        __syncthreads();
    }

    const int qrow = lane >> 2;
    const int qcol = (lane & 3) * 2;
#pragma unroll
    for (int mf = 0; mf < 4; mf++) {
#pragma unroll
        for (int nf = 0; nf < 4; nf++) {
            int col = j0 + wn0 + nf * 8 + qcol;
            float2 bias = __ldg((const float2*)b_enc + (col >> 1));
            int row0 = m0 + wm0 + mf * 16 + qrow;
            float2 v0;
            v0.x = fmaxf(acc[mf][nf][0] + bias.x, 0.0f);
            v0.y = fmaxf(acc[mf][nf][1] + bias.y, 0.0f);
            *(float2*)(dense + (size_t)row0 * WIDTH + col) = v0;
            float2 v1;
            v1.x = fmaxf(acc[mf][nf][2] + bias.x, 0.0f);
            v1.y = fmaxf(acc[mf][nf][3] + bias.y, 0.0f);
            *(float2*)(dense + (size_t)(row0 + 8) * WIDTH + col) = v1;
        }
    }
}

// ---------------- candidate select: radix threshold at rank CAND ---------------
__global__ void __launch_bounds__(256) k_cand()
{
    const int row = blockIdx.x;
    const float* rowp = g_dense + (size_t)row * WIDTH;
    __shared__ uint32_t hist[256];
    __shared__ uint32_t sh_prefix;
    __shared__ int sh_krem;
    __shared__ int sh_cnt;
    const int tid = threadIdx.x;

    if (tid == 0) { sh_prefix = 0; sh_krem = CAND; sh_cnt = 0; }
    __syncthreads();

    for (int pass = 0; pass < 4; pass++) {
        const int shift = 24 - 8 * pass;
        hist[tid] = 0;
        __syncthreads();
        const uint32_t prefix = sh_prefix;
        const uint32_t maskHi = (pass == 0) ? 0u : (0xFFFFFFFFu << (shift + 8));
        for (int i = tid; i < WIDTH; i += 256) {
            uint32_t u = __float_as_uint(rowp[i]);
            if ((u & maskHi) == prefix)
                atomicAdd(&hist[(u >> shift) & 0xFF], 1u);
        }
        __syncthreads();
        if (tid == 0) {
            int need = sh_krem;
            int cum = 0, b = 255;
            for (; b > 0; b--) {
                if (cum + (int)hist[b] >= need) break;
                cum += (int)hist[b];
            }
            sh_prefix = prefix | ((uint32_t)b << shift);
            sh_krem = need - cum;
        }
        __syncthreads();
    }

    const uint32_t T = sh_prefix;   // approx value of rank-CAND element
    for (int i = tid; i < WIDTH; i += 256) {
        uint32_t u = __float_as_uint(rowp[i]);
        if (u >= T) {
            int p = atomicAdd(&sh_cnt, 1);
            if (p < CAP) g_cidx[(size_t)row * CAP + p] = i;
        }
    }
    __syncthreads();
    if (tid == 0) g_ccnt[row] = min(sh_cnt, CAP);
}

// ---------------- exact refine + top-64 + scatter ------------------------------
__global__ void __launch_bounds__(256) k_refine(const float* __restrict__ X,
                                                const float* __restrict__ W_enc,
                                                const float* __restrict__ b_enc,
                                                float* __restrict__ feat)
{
    const int row = blockIdx.x;
    const int tid = threadIdx.x;
    const int lane = tid & 31, w = tid >> 5;
    __shared__ float sx[DM];
    __shared__ float sval[CAP];
    __shared__ int   sidx[CAP];

#pragma unroll
    for (int i = 0; i < DM / 256; i++)
        sx[tid + i * 256] = X[(size_t)row * DM + tid + i * 256];
    sval[tid] = -__int_as_float(0x7f800000);   // -inf
    sidx[tid] = 0x7FFFFFFF;
    const int cnt = g_ccnt[row];
    __syncthreads();

    // exact (compensated fp32) dot products, one candidate per warp, strided
    for (int c = w; c < cnt; c += 8) {
        const int j = g_cidx[(size_t)row * CAP + c];
        const float* wr = W_enc + (size_t)j * DM;
        float s = 0.f, comp = 0.f, es = 0.f;
        for (int d = lane; d < DM; d += 32) {
            float xv = sx[d];
            float wv = __ldg(wr + d);
            float p  = __fmul_rn(xv, wv);
            float e  = __fmaf_rn(xv, wv, -p);   // exact product error
            float y  = __fsub_rn(p, comp);      // Kahan
            float t  = __fadd_rn(s, y);
            comp     = __fsub_rn(__fsub_rn(t, s), y);
            s = t;
            es = __fadd_rn(es, e);
        }
        float tot = __fadd_rn(__fsub_rn(s, comp), es);
#pragma unroll
        for (int o = 16; o; o >>= 1) tot += __shfl_xor_sync(0xffffffffu, tot, o);
        if (lane == 0) {
            sval[c] = fmaxf(tot + __ldg(&b_enc[j]), 0.0f);
            sidx[c] = j;
        }
    }
    __syncthreads();

    // bitonic sort 256 entries: (value desc, index asc)
    for (int k = 2; k <= CAP; k <<= 1) {
        for (int jj = k >> 1; jj > 0; jj >>= 1) {
            int ixj = tid ^ jj;
            if (ixj > tid) {
                bool up = ((tid & k) == 0);
                float va = sval[tid], vb = sval[ixj];
                int   ia = sidx[tid], ib = sidx[ixj];
                bool before = (va > vb) || (va == vb && ia < ib);
                if (up != before) {
                    sval[tid] = vb; sval[ixj] = va;
                    sidx[tid] = ib; sidx[ixj] = ia;
                }
            }
            __syncthreads();
        }
    }

    if (tid < TOPK) {
        int j = sidx[tid];
        float v = sval[tid];
        g_tidx[(size_t)row * TOPK + tid] = j;
        g_tval[(size_t)row * TOPK + tid] = v;
        feat[(size_t)row * WIDTH + j] = v;
    }
}

// ---------------- sparse decoder ----------------------------------------------
__global__ void __launch_bounds__(256) k_decode(const float* __restrict__ b_dec,
                                                float* __restrict__ delta)
{
    const int n = blockIdx.x;
    const int tid = threadIdx.x;
    __shared__ int sidx[TOPK];
    __shared__ float sval[TOPK];
    if (tid < TOPK) {
        sidx[tid] = g_tidx[(size_t)n * TOPK + tid];
        sval[tid] = g_tval[(size_t)n * TOPK + tid];
    }
    __syncthreads();
    float acc[8];
#pragma unroll
    for (int i = 0; i < 8; i++) acc[i] = b_dec[tid + i * 256];
    for (int f = 0; f < TOPK; f++) {
        const float* wr = g_WdecT + (size_t)sidx[f] * DM;
        const float v = sval[f];
#pragma unroll
        for (int i = 0; i < 8; i++) acc[i] = fmaf(v, wr[tid + i * 256], acc[i]);
    }
#pragma unroll
    for (int i = 0; i < 8; i++) delta[(size_t)n * DM + tid + i * 256] = acc[i];
}

// ---------------- launch ------------------------------------------------------
extern "C" void kernel_launch(void* const* d_in, const int* in_sizes, int n_in,
                              void* d_out, int out_size)
{
    const float* X     = (const float*)d_in[0];
    const float* W_enc = (const float*)d_in[1];
    const float* b_enc = (const float*)d_in[2];
    const float* W_dec = (const float*)d_in[3];
    const float* b_dec = (const float*)d_in[4];
    (void)in_sizes; (void)n_in; (void)out_size;

    float* out   = (float*)d_out;
    float* delta = out;                              // [N_TOK, DM]
    float* feat  = out + (size_t)N_TOK * DM;         // [N_TOK, WIDTH]

    cudaFuncSetAttribute(k_encoder, cudaFuncAttributeMaxDynamicSharedMemorySize, ENC_SMEM);

    float* dense;
    cudaGetSymbolAddress((void**)&dense, g_dense);

    k_prep_x<<<2048, 256>>>(X);
    k_prep_w<<<8192, 256>>>(W_enc);
    k_transpose<<<dim3(WIDTH / 32, DM / 32), dim3(32, 8)>>>(W_dec);

    k_encoder<<<dim3(N_TOK / TM, WIDTH / TN), 256, ENC_SMEM>>>(b_enc, dense);

    k_cand<<<N_TOK, 256>>>();
    k_zero_feat<<<2048, 256>>>(feat);
    k_refine<<<N_TOK, 256>>>(X, W_enc, b_enc, feat);
    k_decode<<<N_TOK, 256>>>(b_dec, delta);
}